// round 16
// baseline (speedup 1.0000x reference)
#include <cuda_runtime.h>
#include <cuda_fp16.h>
#include <cstdint>

#define NN 50000
#define EE 800000
#define NBLK 49   // ceil(50000/1024)

// ---------------- scratch (device globals; zero-init at load) ---------------
__device__ __align__(16) __half2 g_xsh[NN * 64];  // transformed feats, half2
__device__ __align__(16) float g_h[NN * 128];
__device__ __align__(16) float4 g_edat[EE];   // (src, ae0, ae1, pad) sorted
__device__ __align__(8) float2 g_aeun[EE];    // (ae0, ae1) edge order
__device__ float g_als[NN];
__device__ float g_ald[NN];
__device__ int   g_deg[NN];      // self-cleaned in k_scan_apply
__device__ int   g_off[NN + 1];
__device__ int   g_cur[NN];
__device__ int   g_bsum[64];
__device__ float g_bnacc[512];   // self-cleaned in agg finalizer
__device__ unsigned g_ctr[2];    // self-cleaned in agg finalizer
__device__ float g_scale[256];
__device__ float g_shift[256];
__device__ float g_ced[16];

// ---------------- bf16 helpers ------------------------------------------------
__device__ __forceinline__ unsigned pack_bf2(float v0, float v1) {
    unsigned u;
    asm("cvt.rn.bf16x2.f32 %0, %1, %2;" : "=r"(u) : "f"(v1), "f"(v0));
    return u;
}

#define MMA_BF16(C, A, B) \
    asm volatile( \
        "mma.sync.aligned.m16n8k16.row.col.f32.bf16.bf16.f32 " \
        "{%0,%1,%2,%3}, {%4,%5,%6,%7}, {%8,%9}, {%0,%1,%2,%3};" \
        : "+f"((C)[0]), "+f"((C)[1]), "+f"((C)[2]), "+f"((C)[3]) \
        : "r"((A)[0]), "r"((A)[1]), "r"((A)[2]), "r"((A)[3]), \
          "r"((B)[0]), "r"((B)[1]))

// ---------------- CSR build -------------------------------------------------
__global__ void k_hist(const int4* __restrict__ dst4) {
    int i = blockIdx.x * blockDim.x + threadIdx.x;
    if (i < EE / 4) {
        int4 d = dst4[i];
        atomicAdd(&g_deg[d.x], 1);
        atomicAdd(&g_deg[d.y], 1);
        atomicAdd(&g_deg[d.z], 1);
        atomicAdd(&g_deg[d.w], 1);
    }
}

__global__ __launch_bounds__(1024) void k_scan_part() {
    __shared__ int ws[32];
    const int tid = threadIdx.x, lane = tid & 31, wid = tid >> 5;
    int i = blockIdx.x * 1024 + tid;
    int v = (i < NN) ? g_deg[i] : 0;
    int x = v;
    #pragma unroll
    for (int o = 1; o < 32; o <<= 1) {
        int t = __shfl_up_sync(0xffffffffu, x, o);
        if (lane >= o) x += t;
    }
    if (lane == 31) ws[wid] = x;
    __syncthreads();
    if (wid == 0) {
        int y = ws[lane];
        #pragma unroll
        for (int o = 1; o < 32; o <<= 1) {
            int t = __shfl_up_sync(0xffffffffu, y, o);
            if (lane >= o) y += t;
        }
        ws[lane] = y;
    }
    __syncthreads();
    int excl = x - v + ((wid > 0) ? ws[wid - 1] : 0);
    if (i < NN) g_off[i] = excl;
    if (tid == 1023) g_bsum[blockIdx.x] = excl + v;
}

__global__ __launch_bounds__(1024) void k_scan_apply() {
    __shared__ int s_pre[2];
    const int tid = threadIdx.x, bid = blockIdx.x;
    if (tid < 64) {
        int v = (tid < bid) ? g_bsum[tid] : 0;
        #pragma unroll
        for (int o = 16; o; o >>= 1) v += __shfl_xor_sync(0xffffffffu, v, o);
        if ((tid & 31) == 0) s_pre[tid >> 5] = v;
    }
    __syncthreads();
    int bp = s_pre[0] + s_pre[1];
    int i = bid * 1024 + tid;
    if (i < NN) {
        int o = g_off[i] + bp;
        g_off[i] = o;
        g_cur[i] = o;
        g_deg[i] = 0;    // self-clean
    }
    if (bid == NBLK - 1 && tid == 1023) g_off[NN] = bp + g_bsum[NBLK - 1];
}

// ---------------- ced for both layers (s2) -----------------------------------
__global__ void k_ced(const float* __restrict__ We0, const float* __restrict__ ae0,
                      const float* __restrict__ We1, const float* __restrict__ ae1) {
    int j = threadIdx.x;
    if (j < 8) {
        float s = 0.f;
        for (int c = 0; c < 128; c++) s += We0[j * 128 + c] * ae0[c];
        g_ced[j] = s;
    } else if (j < 16) {
        int jj = j - 8;
        float s = 0.f;
        for (int c = 0; c < 112; c++) s += We1[jj * 112 + c] * ae1[c];
        g_ced[j] = s;
    }
}

// ---- per-edge edge-attention terms, unsorted (s2, || hist/scan on s1) -------
__global__ void k_aeF(const float* __restrict__ eatt) {
    int e = blockIdx.x * blockDim.x + threadIdx.x;
    if (e >= EE) return;
    const float4* er = (const float4*)(eatt + (size_t)e * 8);
    float4 e0 = er[0], e1 = er[1];
    float ae0 = e0.x * g_ced[0] + e0.y * g_ced[1] + e0.z * g_ced[2] + e0.w * g_ced[3]
              + e1.x * g_ced[4] + e1.y * g_ced[5] + e1.z * g_ced[6] + e1.w * g_ced[7];
    float ae1 = e0.x * g_ced[8] + e0.y * g_ced[9] + e0.z * g_ced[10] + e0.w * g_ced[11]
              + e1.x * g_ced[12] + e1.y * g_ced[13] + e1.z * g_ced[14] + e1.w * g_ced[15];
    g_aeun[e] = make_float2(ae0, ae1);
}

// ---- scatter: packed (src, ae0, ae1) into sorted position (light) -----------
__global__ void k_scatter(const int* __restrict__ src, const int* __restrict__ dst) {
    int e = blockIdx.x * blockDim.x + threadIdx.x;
    if (e >= EE) return;
    float2 q = g_aeun[e];
    int p = atomicAdd(&g_cur[dst[e]], 1);
    g_edat[p] = make_float4(__int_as_float(src[e]), q.x, q.y, 0.f);
}

// ---- bf16x3 tensor-core GEMM -> half2 out (M=128) ----------------------------
template <int COUT, bool PRE>
__launch_bounds__(256)
__global__ void k_gemm(const float* __restrict__ A, const float* __restrict__ W,
                       const float* __restrict__ asrc, const float* __restrict__ adst,
                       __half2* __restrict__ Out) {
    __shared__ unsigned AhiS[128 * 20], AloS[128 * 20];
    __shared__ unsigned BhiS[16 * 136], BloS[16 * 136];
    __shared__ float alsm[2][128], aldm[2][128];
    __shared__ float asv[128], adv[128];

    const int tid = threadIdx.x;
    const int lane = tid & 31, w = tid >> 5;
    const int mrow = (w & 3) * 32;
    const int nwarp = w >> 2;
    const int ncol = nwarp * 64;
    const int row0 = blockIdx.x * 128;

    if (tid < 128) {
        asv[tid] = (tid < COUT) ? asrc[tid] : 0.f;
        adv[tid] = (tid < COUT) ? adst[tid] : 0.f;
    }

    float acc[2][8][4];
    #pragma unroll
    for (int mt = 0; mt < 2; mt++)
        #pragma unroll
        for (int nt = 0; nt < 8; nt++)
            #pragma unroll
            for (int j = 0; j < 4; j++) acc[mt][nt][j] = 0.f;

    float4 aReg[4];
    float2 bReg[8];
    const int bc = tid & 127;
    const int bhalf = tid >> 7;

    auto loadA = [&](int k0) {
        #pragma unroll
        for (int t = 0; t < 4; t++) {
            int idx = tid + t * 256;
            int r = idx >> 3, c4 = (idx & 7) * 4;
            int gr = row0 + r;
            float4 v = make_float4(0.f, 0.f, 0.f, 0.f);
            if (gr < NN) {
                v = *(const float4*)(A + (size_t)gr * 128 + k0 + c4);
                if (PRE) {
                    int ch = k0 + c4;
                    v.x = fmaxf(fmaf(v.x, g_scale[ch + 0], g_shift[ch + 0]), 0.f);
                    v.y = fmaxf(fmaf(v.y, g_scale[ch + 1], g_shift[ch + 1]), 0.f);
                    v.z = fmaxf(fmaf(v.z, g_scale[ch + 2], g_shift[ch + 2]), 0.f);
                    v.w = fmaxf(fmaf(v.w, g_scale[ch + 3], g_shift[ch + 3]), 0.f);
                }
            }
            aReg[t] = v;
        }
    };
    auto loadB = [&](int k0) {
        #pragma unroll
        for (int t = 0; t < 8; t++) {
            int kk = bhalf * 16 + t * 2;
            float w0 = 0.f, w1 = 0.f;
            if (bc < COUT) {
                w0 = W[(size_t)(k0 + kk) * COUT + bc];
                w1 = W[(size_t)(k0 + kk + 1) * COUT + bc];
            }
            bReg[t] = make_float2(w0, w1);
        }
    };

    auto split2 = [](float v0, float v1, unsigned& h, unsigned& l) {
        h = pack_bf2(v0, v1);
        float h0 = __uint_as_float(h << 16);
        float h1 = __uint_as_float(h & 0xFFFF0000u);
        l = pack_bf2(v0 - h0, v1 - h1);
    };

    loadA(0);
    loadB(0);

    for (int k0 = 0; k0 < 128; k0 += 32) {
        #pragma unroll
        for (int t = 0; t < 4; t++) {
            int idx = tid + t * 256;
            int r = idx >> 3;
            int p0 = (idx & 7) * 2;
            unsigned h, l;
            split2(aReg[t].x, aReg[t].y, h, l);
            AhiS[r * 20 + p0] = h; AloS[r * 20 + p0] = l;
            split2(aReg[t].z, aReg[t].w, h, l);
            AhiS[r * 20 + p0 + 1] = h; AloS[r * 20 + p0 + 1] = l;
        }
        #pragma unroll
        for (int t = 0; t < 8; t++) {
            int pk = bhalf * 8 + t;
            unsigned h, l;
            split2(bReg[t].x, bReg[t].y, h, l);
            BhiS[pk * 136 + bc] = h; BloS[pk * 136 + bc] = l;
        }
        __syncthreads();

        if (k0 + 32 < 128) {
            loadA(k0 + 32);
            loadB(k0 + 32);
        }

        #pragma unroll
        for (int ks = 0; ks < 2; ks++) {
            const int pa = ks * 8 + (lane & 3);
            unsigned ah[2][4], al[2][4];
            #pragma unroll
            for (int mt = 0; mt < 2; mt++) {
                int rb = mrow + mt * 16 + (lane >> 2);
                ah[mt][0] = AhiS[rb * 20 + pa];
                ah[mt][1] = AhiS[(rb + 8) * 20 + pa];
                ah[mt][2] = AhiS[rb * 20 + pa + 4];
                ah[mt][3] = AhiS[(rb + 8) * 20 + pa + 4];
                al[mt][0] = AloS[rb * 20 + pa];
                al[mt][1] = AloS[(rb + 8) * 20 + pa];
                al[mt][2] = AloS[rb * 20 + pa + 4];
                al[mt][3] = AloS[(rb + 8) * 20 + pa + 4];
            }
            unsigned bh[8][2], bl[8][2];
            #pragma unroll
            for (int nt = 0; nt < 8; nt++) {
                int cb = ncol + nt * 8 + (lane >> 2);
                bh[nt][0] = BhiS[pa * 136 + cb];
                bh[nt][1] = BhiS[(pa + 4) * 136 + cb];
                bl[nt][0] = BloS[pa * 136 + cb];
                bl[nt][1] = BloS[(pa + 4) * 136 + cb];
            }
            #pragma unroll
            for (int mt = 0; mt < 2; mt++)
                #pragma unroll
                for (int nt = 0; nt < 8; nt++) {
                    MMA_BF16(acc[mt][nt], ah[mt], bl[nt]);
                    MMA_BF16(acc[mt][nt], al[mt], bh[nt]);
                    MMA_BF16(acc[mt][nt], ah[mt], bh[nt]);
                }
        }
        __syncthreads();
    }

    // epilogue: half2 store + attention-logit partials (from fp32 accs)
    float ps[4], pd[4];
    #pragma unroll
    for (int j = 0; j < 4; j++) { ps[j] = 0.f; pd[j] = 0.f; }

    #pragma unroll
    for (int mt = 0; mt < 2; mt++) {
        #pragma unroll
        for (int nt = 0; nt < 8; nt++) {
            float* c = acc[mt][nt];
            int r0 = mrow + mt * 16 + (lane >> 2);
            int c0 = ncol + nt * 8 + (lane & 3) * 2;
            int gr0 = row0 + r0, gr1 = gr0 + 8;
            if (c0 < COUT) {
                if (gr0 < NN)
                    Out[(size_t)gr0 * (COUT / 2) + (c0 >> 1)] = __floats2half2_rn(c[0], c[1]);
                if (gr1 < NN)
                    Out[(size_t)gr1 * (COUT / 2) + (c0 >> 1)] = __floats2half2_rn(c[2], c[3]);
            }
            float a0 = asv[c0], a1 = asv[c0 + 1];
            float d0 = adv[c0], d1 = adv[c0 + 1];
            ps[mt * 2 + 0] += c[0] * a0 + c[1] * a1;
            ps[mt * 2 + 1] += c[2] * a0 + c[3] * a1;
            pd[mt * 2 + 0] += c[0] * d0 + c[1] * d1;
            pd[mt * 2 + 1] += c[2] * d0 + c[3] * d1;
        }
    }
    #pragma unroll
    for (int j = 0; j < 4; j++) {
        ps[j] += __shfl_xor_sync(0xffffffffu, ps[j], 1);
        ps[j] += __shfl_xor_sync(0xffffffffu, ps[j], 2);
        pd[j] += __shfl_xor_sync(0xffffffffu, pd[j], 1);
        pd[j] += __shfl_xor_sync(0xffffffffu, pd[j], 2);
    }
    if ((lane & 3) == 0) {
        #pragma unroll
        for (int mt = 0; mt < 2; mt++) {
            int rb = mrow + mt * 16 + (lane >> 2);
            alsm[nwarp][rb] = ps[mt * 2 + 0];
            alsm[nwarp][rb + 8] = ps[mt * 2 + 1];
            aldm[nwarp][rb] = pd[mt * 2 + 0];
            aldm[nwarp][rb + 8] = pd[mt * 2 + 1];
        }
    }
    __syncthreads();
    if (tid < 128) {
        int gr = row0 + tid;
        if (gr < NN) {
            g_als[gr] = alsm[0][tid] + alsm[1][tid];
            g_ald[gr] = aldm[0][tid] + aldm[1][tid];
        }
    }
}

// ------- 8-nodes-per-warp agg (R14) + __ldcg on L2-bound loads ---------------
template <int C, int AEC>
__launch_bounds__(256)
__global__ void k_agg(const float* __restrict__ bias, float* __restrict__ out,
                      const float* __restrict__ bgam, const float* __restrict__ bbet,
                      int accoff, int scoff, int cidx) {
    __shared__ float s_sum[C];
    __shared__ float s_sq[C];
    __shared__ unsigned s_ticket;
    const int tid = threadIdx.x;
    const int lane = tid & 31;
    for (int c = tid; c < C; c += 256) { s_sum[c] = 0.f; s_sq[c] = 0.f; }
    __syncthreads();

    constexpr int NV = C / 4;
    constexpr int H2 = C / 2;
    const bool act = lane < NV;

    int wg = (blockIdx.x * 256 + tid) >> 5;
    int n0 = wg * 8;
    int n1 = (n0 + 8 < NN) ? n0 + 8 : NN;

    for (int gw = n0; gw < n1; gw++) {
        int beg = g_off[gw], end = g_off[gw + 1];
        float aldv = g_ald[gw];

        float den = 0.f;
        float4 acc = make_float4(0.f, 0.f, 0.f, 0.f);
        int p = beg;
        for (; p + 4 <= end; p += 4) {
            float4 E0 = __ldcg(&g_edat[p]),     E1 = __ldcg(&g_edat[p + 1]);
            float4 E2 = __ldcg(&g_edat[p + 2]), E3 = __ldcg(&g_edat[p + 3]);
            int s0 = __float_as_int(E0.x), s1 = __float_as_int(E1.x);
            int s2 = __float_as_int(E2.x), s3 = __float_as_int(E3.x);
            float a0 = g_als[s0] + aldv + (AEC ? E0.z : E0.y);
            float a1 = g_als[s1] + aldv + (AEC ? E1.z : E1.y);
            float a2 = g_als[s2] + aldv + (AEC ? E2.z : E2.y);
            float a3 = g_als[s3] + aldv + (AEC ? E3.z : E3.y);
            a0 = (a0 > 0.f) ? a0 : 0.2f * a0;
            a1 = (a1 > 0.f) ? a1 : 0.2f * a1;
            a2 = (a2 > 0.f) ? a2 : 0.2f * a2;
            a3 = (a3 > 0.f) ? a3 : 0.2f * a3;
            float w0 = __expf(a0), w1 = __expf(a1);
            float w2 = __expf(a2), w3 = __expf(a3);
            den += (w0 + w1) + (w2 + w3);
            if (act) {
                uint2 u0 = __ldcg((const uint2*)(g_xsh + (size_t)s0 * H2 + lane * 2));
                uint2 u1 = __ldcg((const uint2*)(g_xsh + (size_t)s1 * H2 + lane * 2));
                uint2 u2 = __ldcg((const uint2*)(g_xsh + (size_t)s2 * H2 + lane * 2));
                uint2 u3 = __ldcg((const uint2*)(g_xsh + (size_t)s3 * H2 + lane * 2));
                float2 f0a = __half22float2(*(__half2*)&u0.x), f0b = __half22float2(*(__half2*)&u0.y);
                float2 f1a = __half22float2(*(__half2*)&u1.x), f1b = __half22float2(*(__half2*)&u1.y);
                float2 f2a = __half22float2(*(__half2*)&u2.x), f2b = __half22float2(*(__half2*)&u2.y);
                float2 f3a = __half22float2(*(__half2*)&u3.x), f3b = __half22float2(*(__half2*)&u3.y);
                acc.x += (w0 * f0a.x + w1 * f1a.x) + (w2 * f2a.x + w3 * f3a.x);
                acc.y += (w0 * f0a.y + w1 * f1a.y) + (w2 * f2a.y + w3 * f3a.y);
                acc.z += (w0 * f0b.x + w1 * f1b.x) + (w2 * f2b.x + w3 * f3b.x);
                acc.w += (w0 * f0b.y + w1 * f1b.y) + (w2 * f2b.y + w3 * f3b.y);
            }
        }
        for (; p < end; p++) {
            float4 E0 = __ldcg(&g_edat[p]);
            int s0 = __float_as_int(E0.x);
            float a0 = g_als[s0] + aldv + (AEC ? E0.z : E0.y);
            a0 = (a0 > 0.f) ? a0 : 0.2f * a0;
            float w0 = __expf(a0);
            den += w0;
            if (act) {
                uint2 u0 = __ldcg((const uint2*)(g_xsh + (size_t)s0 * H2 + lane * 2));
                float2 f0a = __half22float2(*(__half2*)&u0.x), f0b = __half22float2(*(__half2*)&u0.y);
                acc.x += w0 * f0a.x; acc.y += w0 * f0a.y;
                acc.z += w0 * f0b.x; acc.w += w0 * f0b.y;
            }
        }
        float inv = (end > beg) ? 1.f / den : 0.f;
        if (act) {
            float4 b = *(const float4*)(bias + lane * 4);
            acc.x = fmaf(acc.x, inv, b.x);
            acc.y = fmaf(acc.y, inv, b.y);
            acc.z = fmaf(acc.z, inv, b.z);
            acc.w = fmaf(acc.w, inv, b.w);
            *(float4*)(out + (size_t)gw * C + lane * 4) = acc;
            int c = lane * 4;
            atomicAdd(&s_sum[c + 0], acc.x); atomicAdd(&s_sq[c + 0], acc.x * acc.x);
            atomicAdd(&s_sum[c + 1], acc.y); atomicAdd(&s_sq[c + 1], acc.y * acc.y);
            atomicAdd(&s_sum[c + 2], acc.z); atomicAdd(&s_sq[c + 2], acc.z * acc.z);
            atomicAdd(&s_sum[c + 3], acc.w); atomicAdd(&s_sq[c + 3], acc.w * acc.w);
        }
    }
    __syncthreads();
    for (int c = tid; c < C; c += 256) {
        atomicAdd(&g_bnacc[accoff + c], s_sum[c]);
        atomicAdd(&g_bnacc[accoff + 128 + c], s_sq[c]);
    }
    // last-block BN finalize
    __threadfence();
    __syncthreads();
    if (tid == 0) s_ticket = atomicAdd(&g_ctr[cidx], 1u);
    __syncthreads();
    if (s_ticket == gridDim.x - 1) {
        __threadfence();
        if (tid < C) {
            float sum = __ldcg(&g_bnacc[accoff + tid]);
            float sq  = __ldcg(&g_bnacc[accoff + 128 + tid]);
            float mean = sum * (1.f / NN);
            float var = sq * (1.f / NN) - mean * mean;
            float sc = bgam[tid] * rsqrtf(var + 1e-5f);
            g_scale[scoff + tid] = sc;
            g_shift[scoff + tid] = bbet[tid] - mean * sc;
            g_bnacc[accoff + tid] = 0.f;
            g_bnacc[accoff + 128 + tid] = 0.f;
        }
        if (tid == 0) g_ctr[cidx] = 0u;
    }
}

// ---------------- final BN apply ---------------------------------------------
__global__ void k_out(const float* __restrict__ h, float* __restrict__ out) {
    int idx = blockIdx.x * blockDim.x + threadIdx.x;
    int i4 = idx * 4;
    if (i4 < NN * 112) {
        int c = i4 % 112;
        float4 v = *(const float4*)(h + i4);
        v.x = fmaf(v.x, g_scale[128 + c + 0], g_shift[128 + c + 0]);
        v.y = fmaf(v.y, g_scale[128 + c + 1], g_shift[128 + c + 1]);
        v.z = fmaf(v.z, g_scale[128 + c + 2], g_shift[128 + c + 2]);
        v.w = fmaf(v.w, g_scale[128 + c + 3], g_shift[128 + c + 3]);
        *(float4*)(out + i4) = v;
    }
}

// ---------------- launch -----------------------------------------------------
extern "C" void kernel_launch(void* const* d_in, const int* in_sizes, int n_in,
                              void* d_out, int out_size) {
    const float* x    = (const float*)d_in[0];
    const int*   ei   = (const int*)d_in[1];
    const float* eatt = (const float*)d_in[2];
    const float* W0   = (const float*)d_in[3];
    const float* as0  = (const float*)d_in[4];
    const float* ad0  = (const float*)d_in[5];
    const float* We0  = (const float*)d_in[6];
    const float* ae0  = (const float*)d_in[7];
    const float* b0   = (const float*)d_in[8];
    const float* W1   = (const float*)d_in[9];
    const float* as1  = (const float*)d_in[10];
    const float* ad1  = (const float*)d_in[11];
    const float* We1  = (const float*)d_in[12];
    const float* ae1  = (const float*)d_in[13];
    const float* b1   = (const float*)d_in[14];
    const float* bng  = (const float*)d_in[15];
    const float* bnb  = (const float*)d_in[16];
    const float* bfg  = (const float*)d_in[17];
    const float* bfb  = (const float*)d_in[18];
    float* out = (float*)d_out;

    const int* src = ei;
    const int* dst = ei + EE;

    __half2* p_xsh = nullptr;
    float* p_h = nullptr;
    cudaGetSymbolAddress((void**)&p_xsh, g_xsh);
    cudaGetSymbolAddress((void**)&p_h, g_h);

    static cudaStream_t s1 = nullptr, s2 = nullptr;
    static cudaEvent_t evFork = nullptr, evJoin = nullptr, ev2 = nullptr;
    if (!s1) {
        cudaStreamCreateWithFlags(&s1, cudaStreamNonBlocking);
        cudaStreamCreateWithFlags(&s2, cudaStreamNonBlocking);
        cudaEventCreateWithFlags(&evFork, cudaEventDisableTiming);
        cudaEventCreateWithFlags(&evJoin, cudaEventDisableTiming);
        cudaEventCreateWithFlags(&ev2, cudaEventDisableTiming);
    }

    const int TB = 256;
    const int gE = (EE + TB - 1) / TB;
    const int gE4 = (EE / 4 + TB - 1) / TB;
    const int gW8 = (NN + 63) / 64;
    const int gG = (NN + 127) / 128;

    // ---- fork: s1 = hist/scan, s2 = ced+aeF; join at scatter; gemm0 on main
    cudaEventRecord(evFork, 0);
    cudaStreamWaitEvent(s1, evFork, 0);
    cudaStreamWaitEvent(s2, evFork, 0);

    k_hist<<<gE4, TB, 0, s1>>>((const int4*)dst);
    k_scan_part<<<NBLK, 1024, 0, s1>>>();
    k_scan_apply<<<NBLK, 1024, 0, s1>>>();
    k_gemm<128, false><<<gG, 256>>>(x, W0, as0, ad0, p_xsh);    // profiled slot
    k_ced<<<1, 32, 0, s2>>>(We0, ae0, We1, ae1);
    k_aeF<<<gE, TB, 0, s2>>>(eatt);
    cudaEventRecord(ev2, s2);
    cudaStreamWaitEvent(s1, ev2, 0);
    k_scatter<<<gE, TB, 0, s1>>>(src, dst);
    cudaEventRecord(evJoin, s1);

    cudaStreamWaitEvent(0, evJoin, 0);

    // ---- layer 0 (alpha inline, BN finalize fused)
    k_agg<128, 0><<<gW8, TB>>>(b0, p_h, bng, bnb, 0, 0, 0);

    // ---- layer 1 (BN+relu fused into A-load; alpha inline; BN fused)
    k_gemm<112, true><<<gG, 256>>>(p_h, W1, as1, ad1, p_xsh);
    k_agg<112, 1><<<gW8, TB>>>(b1, p_h, bfg, bfb, 256, 128, 1);
    k_out<<<(NN * 112 / 4 + TB - 1) / TB, TB>>>(p_h, out);
}

// round 17
// speedup vs baseline: 1.1348x; 1.1348x over previous
#include <cuda_runtime.h>
#include <cuda_fp16.h>
#include <cstdint>

#define NN 50000
#define EE 800000
#define NBLK 49   // ceil(50000/1024)

// ---------------- scratch (device globals; zero-init at load) ---------------
__device__ __align__(16) __half2 g_xsh[NN * 64];  // transformed feats, half2
__device__ __align__(16) float g_h[NN * 128];
__device__ __align__(16) float4 g_edat[EE];   // (src, ae0, ae1, pad) sorted
__device__ __align__(8) float2 g_aeun[EE];    // (ae0, ae1) edge order
__device__ float g_als[NN];
__device__ float g_ald[NN];
__device__ int   g_deg[NN];      // self-cleaned in k_scan_apply
__device__ int   g_off[NN + 1];
__device__ int   g_cur[NN];
__device__ int   g_bsum[64];
__device__ float g_bnacc[512];   // self-cleaned in agg finalizer
__device__ unsigned g_ctr[2];    // self-cleaned in agg finalizer
__device__ float g_scale[256];
__device__ float g_shift[256];
__device__ float g_ced[16];

// ---------------- bf16 helpers ------------------------------------------------
__device__ __forceinline__ unsigned pack_bf2(float v0, float v1) {
    unsigned u;
    asm("cvt.rn.bf16x2.f32 %0, %1, %2;" : "=r"(u) : "f"(v1), "f"(v0));
    return u;
}

#define MMA_BF16(C, A, B) \
    asm volatile( \
        "mma.sync.aligned.m16n8k16.row.col.f32.bf16.bf16.f32 " \
        "{%0,%1,%2,%3}, {%4,%5,%6,%7}, {%8,%9}, {%0,%1,%2,%3};" \
        : "+f"((C)[0]), "+f"((C)[1]), "+f"((C)[2]), "+f"((C)[3]) \
        : "r"((A)[0]), "r"((A)[1]), "r"((A)[2]), "r"((A)[3]), \
          "r"((B)[0]), "r"((B)[1]))

// ---------------- CSR build -------------------------------------------------
__global__ void k_hist(const int4* __restrict__ dst4) {
    int i = blockIdx.x * blockDim.x + threadIdx.x;
    if (i < EE / 4) {
        int4 d = dst4[i];
        atomicAdd(&g_deg[d.x], 1);
        atomicAdd(&g_deg[d.y], 1);
        atomicAdd(&g_deg[d.z], 1);
        atomicAdd(&g_deg[d.w], 1);
    }
}

__global__ __launch_bounds__(1024) void k_scan_part() {
    __shared__ int ws[32];
    const int tid = threadIdx.x, lane = tid & 31, wid = tid >> 5;
    int i = blockIdx.x * 1024 + tid;
    int v = (i < NN) ? g_deg[i] : 0;
    int x = v;
    #pragma unroll
    for (int o = 1; o < 32; o <<= 1) {
        int t = __shfl_up_sync(0xffffffffu, x, o);
        if (lane >= o) x += t;
    }
    if (lane == 31) ws[wid] = x;
    __syncthreads();
    if (wid == 0) {
        int y = ws[lane];
        #pragma unroll
        for (int o = 1; o < 32; o <<= 1) {
            int t = __shfl_up_sync(0xffffffffu, y, o);
            if (lane >= o) y += t;
        }
        ws[lane] = y;
    }
    __syncthreads();
    int excl = x - v + ((wid > 0) ? ws[wid - 1] : 0);
    if (i < NN) g_off[i] = excl;
    if (tid == 1023) g_bsum[blockIdx.x] = excl + v;
}

__global__ __launch_bounds__(1024) void k_scan_apply() {
    __shared__ int s_pre[2];
    const int tid = threadIdx.x, bid = blockIdx.x;
    if (tid < 64) {
        int v = (tid < bid) ? g_bsum[tid] : 0;
        #pragma unroll
        for (int o = 16; o; o >>= 1) v += __shfl_xor_sync(0xffffffffu, v, o);
        if ((tid & 31) == 0) s_pre[tid >> 5] = v;
    }
    __syncthreads();
    int bp = s_pre[0] + s_pre[1];
    int i = bid * 1024 + tid;
    if (i < NN) {
        int o = g_off[i] + bp;
        g_off[i] = o;
        g_cur[i] = o;
        g_deg[i] = 0;    // self-clean
    }
    if (bid == NBLK - 1 && tid == 1023) g_off[NN] = bp + g_bsum[NBLK - 1];
}

// ---------------- ced for both layers (s2) -----------------------------------
__global__ void k_ced(const float* __restrict__ We0, const float* __restrict__ ae0,
                      const float* __restrict__ We1, const float* __restrict__ ae1) {
    int j = threadIdx.x;
    if (j < 8) {
        float s = 0.f;
        for (int c = 0; c < 128; c++) s += We0[j * 128 + c] * ae0[c];
        g_ced[j] = s;
    } else if (j < 16) {
        int jj = j - 8;
        float s = 0.f;
        for (int c = 0; c < 112; c++) s += We1[jj * 112 + c] * ae1[c];
        g_ced[j] = s;
    }
}

// ---- per-edge edge-attention terms, unsorted (s2, || hist/scan on s1) -------
__global__ void k_aeF(const float* __restrict__ eatt) {
    int e = blockIdx.x * blockDim.x + threadIdx.x;
    if (e >= EE) return;
    const float4* er = (const float4*)(eatt + (size_t)e * 8);
    float4 e0 = er[0], e1 = er[1];
    float ae0 = e0.x * g_ced[0] + e0.y * g_ced[1] + e0.z * g_ced[2] + e0.w * g_ced[3]
              + e1.x * g_ced[4] + e1.y * g_ced[5] + e1.z * g_ced[6] + e1.w * g_ced[7];
    float ae1 = e0.x * g_ced[8] + e0.y * g_ced[9] + e0.z * g_ced[10] + e0.w * g_ced[11]
              + e1.x * g_ced[12] + e1.y * g_ced[13] + e1.z * g_ced[14] + e1.w * g_ced[15];
    g_aeun[e] = make_float2(ae0, ae1);
}

// ---- scatter: packed (src, ae0, ae1) into sorted position (light) -----------
__global__ void k_scatter(const int* __restrict__ src, const int* __restrict__ dst) {
    int e = blockIdx.x * blockDim.x + threadIdx.x;
    if (e >= EE) return;
    float2 q = g_aeun[e];
    int p = atomicAdd(&g_cur[dst[e]], 1);
    g_edat[p] = make_float4(__int_as_float(src[e]), q.x, q.y, 0.f);
}

// ---- bf16x3 tensor-core GEMM -> half2 out (M=128), 2 CTAs/SM target ----------
template <int COUT, bool PRE>
__launch_bounds__(256, 2)
__global__ void k_gemm(const float* __restrict__ A, const float* __restrict__ W,
                       const float* __restrict__ asrc, const float* __restrict__ adst,
                       __half2* __restrict__ Out) {
    __shared__ unsigned AhiS[128 * 20], AloS[128 * 20];
    __shared__ unsigned BhiS[16 * 136], BloS[16 * 136];
    __shared__ float alsm[2][128], aldm[2][128];
    __shared__ float asv[128], adv[128];

    const int tid = threadIdx.x;
    const int lane = tid & 31, w = tid >> 5;
    const int mrow = (w & 3) * 32;
    const int nwarp = w >> 2;
    const int ncol = nwarp * 64;
    const int row0 = blockIdx.x * 128;

    if (tid < 128) {
        asv[tid] = (tid < COUT) ? asrc[tid] : 0.f;
        adv[tid] = (tid < COUT) ? adst[tid] : 0.f;
    }

    float acc[2][8][4];
    #pragma unroll
    for (int mt = 0; mt < 2; mt++)
        #pragma unroll
        for (int nt = 0; nt < 8; nt++)
            #pragma unroll
            for (int j = 0; j < 4; j++) acc[mt][nt][j] = 0.f;

    float4 aReg[4];
    float2 bReg[8];
    const int bc = tid & 127;
    const int bhalf = tid >> 7;

    auto loadA = [&](int k0) {
        #pragma unroll
        for (int t = 0; t < 4; t++) {
            int idx = tid + t * 256;
            int r = idx >> 3, c4 = (idx & 7) * 4;
            int gr = row0 + r;
            float4 v = make_float4(0.f, 0.f, 0.f, 0.f);
            if (gr < NN) {
                v = *(const float4*)(A + (size_t)gr * 128 + k0 + c4);
                if (PRE) {
                    int ch = k0 + c4;
                    v.x = fmaxf(fmaf(v.x, g_scale[ch + 0], g_shift[ch + 0]), 0.f);
                    v.y = fmaxf(fmaf(v.y, g_scale[ch + 1], g_shift[ch + 1]), 0.f);
                    v.z = fmaxf(fmaf(v.z, g_scale[ch + 2], g_shift[ch + 2]), 0.f);
                    v.w = fmaxf(fmaf(v.w, g_scale[ch + 3], g_shift[ch + 3]), 0.f);
                }
            }
            aReg[t] = v;
        }
    };
    auto loadB = [&](int k0) {
        #pragma unroll
        for (int t = 0; t < 8; t++) {
            int kk = bhalf * 16 + t * 2;
            float w0 = 0.f, w1 = 0.f;
            if (bc < COUT) {
                w0 = W[(size_t)(k0 + kk) * COUT + bc];
                w1 = W[(size_t)(k0 + kk + 1) * COUT + bc];
            }
            bReg[t] = make_float2(w0, w1);
        }
    };

    auto split2 = [](float v0, float v1, unsigned& h, unsigned& l) {
        h = pack_bf2(v0, v1);
        float h0 = __uint_as_float(h << 16);
        float h1 = __uint_as_float(h & 0xFFFF0000u);
        l = pack_bf2(v0 - h0, v1 - h1);
    };

    loadA(0);
    loadB(0);

    for (int k0 = 0; k0 < 128; k0 += 32) {
        #pragma unroll
        for (int t = 0; t < 4; t++) {
            int idx = tid + t * 256;
            int r = idx >> 3;
            int p0 = (idx & 7) * 2;
            unsigned h, l;
            split2(aReg[t].x, aReg[t].y, h, l);
            AhiS[r * 20 + p0] = h; AloS[r * 20 + p0] = l;
            split2(aReg[t].z, aReg[t].w, h, l);
            AhiS[r * 20 + p0 + 1] = h; AloS[r * 20 + p0 + 1] = l;
        }
        #pragma unroll
        for (int t = 0; t < 8; t++) {
            int pk = bhalf * 8 + t;
            unsigned h, l;
            split2(bReg[t].x, bReg[t].y, h, l);
            BhiS[pk * 136 + bc] = h; BloS[pk * 136 + bc] = l;
        }
        __syncthreads();

        if (k0 + 32 < 128) {
            loadA(k0 + 32);
            loadB(k0 + 32);
        }

        #pragma unroll
        for (int ks = 0; ks < 2; ks++) {
            const int pa = ks * 8 + (lane & 3);
            unsigned ah[2][4], al[2][4];
            #pragma unroll
            for (int mt = 0; mt < 2; mt++) {
                int rb = mrow + mt * 16 + (lane >> 2);
                ah[mt][0] = AhiS[rb * 20 + pa];
                ah[mt][1] = AhiS[(rb + 8) * 20 + pa];
                ah[mt][2] = AhiS[rb * 20 + pa + 4];
                ah[mt][3] = AhiS[(rb + 8) * 20 + pa + 4];
                al[mt][0] = AloS[rb * 20 + pa];
                al[mt][1] = AloS[(rb + 8) * 20 + pa];
                al[mt][2] = AloS[rb * 20 + pa + 4];
                al[mt][3] = AloS[(rb + 8) * 20 + pa + 4];
            }
            unsigned bh[8][2], bl[8][2];
            #pragma unroll
            for (int nt = 0; nt < 8; nt++) {
                int cb = ncol + nt * 8 + (lane >> 2);
                bh[nt][0] = BhiS[pa * 136 + cb];
                bh[nt][1] = BhiS[(pa + 4) * 136 + cb];
                bl[nt][0] = BloS[pa * 136 + cb];
                bl[nt][1] = BloS[(pa + 4) * 136 + cb];
            }
            #pragma unroll
            for (int mt = 0; mt < 2; mt++)
                #pragma unroll
                for (int nt = 0; nt < 8; nt++) {
                    MMA_BF16(acc[mt][nt], ah[mt], bl[nt]);
                    MMA_BF16(acc[mt][nt], al[mt], bh[nt]);
                    MMA_BF16(acc[mt][nt], ah[mt], bh[nt]);
                }
        }
        __syncthreads();
    }

    // epilogue: half2 store + attention-logit partials (from fp32 accs)
    float ps[4], pd[4];
    #pragma unroll
    for (int j = 0; j < 4; j++) { ps[j] = 0.f; pd[j] = 0.f; }

    #pragma unroll
    for (int mt = 0; mt < 2; mt++) {
        #pragma unroll
        for (int nt = 0; nt < 8; nt++) {
            float* c = acc[mt][nt];
            int r0 = mrow + mt * 16 + (lane >> 2);
            int c0 = ncol + nt * 8 + (lane & 3) * 2;
            int gr0 = row0 + r0, gr1 = gr0 + 8;
            if (c0 < COUT) {
                if (gr0 < NN)
                    Out[(size_t)gr0 * (COUT / 2) + (c0 >> 1)] = __floats2half2_rn(c[0], c[1]);
                if (gr1 < NN)
                    Out[(size_t)gr1 * (COUT / 2) + (c0 >> 1)] = __floats2half2_rn(c[2], c[3]);
            }
            float a0 = asv[c0], a1 = asv[c0 + 1];
            float d0 = adv[c0], d1 = adv[c0 + 1];
            ps[mt * 2 + 0] += c[0] * a0 + c[1] * a1;
            ps[mt * 2 + 1] += c[2] * a0 + c[3] * a1;
            pd[mt * 2 + 0] += c[0] * d0 + c[1] * d1;
            pd[mt * 2 + 1] += c[2] * d0 + c[3] * d1;
        }
    }
    #pragma unroll
    for (int j = 0; j < 4; j++) {
        ps[j] += __shfl_xor_sync(0xffffffffu, ps[j], 1);
        ps[j] += __shfl_xor_sync(0xffffffffu, ps[j], 2);
        pd[j] += __shfl_xor_sync(0xffffffffu, pd[j], 1);
        pd[j] += __shfl_xor_sync(0xffffffffu, pd[j], 2);
    }
    if ((lane & 3) == 0) {
        #pragma unroll
        for (int mt = 0; mt < 2; mt++) {
            int rb = mrow + mt * 16 + (lane >> 2);
            alsm[nwarp][rb] = ps[mt * 2 + 0];
            alsm[nwarp][rb + 8] = ps[mt * 2 + 1];
            aldm[nwarp][rb] = pd[mt * 2 + 0];
            aldm[nwarp][rb + 8] = pd[mt * 2 + 1];
        }
    }
    __syncthreads();
    if (tid < 128) {
        int gr = row0 + tid;
        if (gr < NN) {
            g_als[gr] = alsm[0][tid] + alsm[1][tid];
            g_ald[gr] = aldm[0][tid] + aldm[1][tid];
        }
    }
}

// ------- 8-nodes-per-warp agg (R14, unmodified) -------------------------------
template <int C, int AEC>
__launch_bounds__(256)
__global__ void k_agg(const float* __restrict__ bias, float* __restrict__ out,
                      const float* __restrict__ bgam, const float* __restrict__ bbet,
                      int accoff, int scoff, int cidx) {
    __shared__ float s_sum[C];
    __shared__ float s_sq[C];
    __shared__ unsigned s_ticket;
    const int tid = threadIdx.x;
    const int lane = tid & 31;
    for (int c = tid; c < C; c += 256) { s_sum[c] = 0.f; s_sq[c] = 0.f; }
    __syncthreads();

    constexpr int NV = C / 4;
    constexpr int H2 = C / 2;
    const bool act = lane < NV;

    int wg = (blockIdx.x * 256 + tid) >> 5;
    int n0 = wg * 8;
    int n1 = (n0 + 8 < NN) ? n0 + 8 : NN;

    for (int gw = n0; gw < n1; gw++) {
        int beg = g_off[gw], end = g_off[gw + 1];
        float aldv = g_ald[gw];

        float den = 0.f;
        float4 acc = make_float4(0.f, 0.f, 0.f, 0.f);
        int p = beg;
        for (; p + 4 <= end; p += 4) {
            float4 E0 = g_edat[p],     E1 = g_edat[p + 1];
            float4 E2 = g_edat[p + 2], E3 = g_edat[p + 3];
            int s0 = __float_as_int(E0.x), s1 = __float_as_int(E1.x);
            int s2 = __float_as_int(E2.x), s3 = __float_as_int(E3.x);
            float a0 = g_als[s0] + aldv + (AEC ? E0.z : E0.y);
            float a1 = g_als[s1] + aldv + (AEC ? E1.z : E1.y);
            float a2 = g_als[s2] + aldv + (AEC ? E2.z : E2.y);
            float a3 = g_als[s3] + aldv + (AEC ? E3.z : E3.y);
            a0 = (a0 > 0.f) ? a0 : 0.2f * a0;
            a1 = (a1 > 0.f) ? a1 : 0.2f * a1;
            a2 = (a2 > 0.f) ? a2 : 0.2f * a2;
            a3 = (a3 > 0.f) ? a3 : 0.2f * a3;
            float w0 = __expf(a0), w1 = __expf(a1);
            float w2 = __expf(a2), w3 = __expf(a3);
            den += (w0 + w1) + (w2 + w3);
            if (act) {
                uint2 u0 = *(const uint2*)(g_xsh + (size_t)s0 * H2 + lane * 2);
                uint2 u1 = *(const uint2*)(g_xsh + (size_t)s1 * H2 + lane * 2);
                uint2 u2 = *(const uint2*)(g_xsh + (size_t)s2 * H2 + lane * 2);
                uint2 u3 = *(const uint2*)(g_xsh + (size_t)s3 * H2 + lane * 2);
                float2 f0a = __half22float2(*(__half2*)&u0.x), f0b = __half22float2(*(__half2*)&u0.y);
                float2 f1a = __half22float2(*(__half2*)&u1.x), f1b = __half22float2(*(__half2*)&u1.y);
                float2 f2a = __half22float2(*(__half2*)&u2.x), f2b = __half22float2(*(__half2*)&u2.y);
                float2 f3a = __half22float2(*(__half2*)&u3.x), f3b = __half22float2(*(__half2*)&u3.y);
                acc.x += (w0 * f0a.x + w1 * f1a.x) + (w2 * f2a.x + w3 * f3a.x);
                acc.y += (w0 * f0a.y + w1 * f1a.y) + (w2 * f2a.y + w3 * f3a.y);
                acc.z += (w0 * f0b.x + w1 * f1b.x) + (w2 * f2b.x + w3 * f3b.x);
                acc.w += (w0 * f0b.y + w1 * f1b.y) + (w2 * f2b.y + w3 * f3b.y);
            }
        }
        for (; p < end; p++) {
            float4 E0 = g_edat[p];
            int s0 = __float_as_int(E0.x);
            float a0 = g_als[s0] + aldv + (AEC ? E0.z : E0.y);
            a0 = (a0 > 0.f) ? a0 : 0.2f * a0;
            float w0 = __expf(a0);
            den += w0;
            if (act) {
                uint2 u0 = *(const uint2*)(g_xsh + (size_t)s0 * H2 + lane * 2);
                float2 f0a = __half22float2(*(__half2*)&u0.x), f0b = __half22float2(*(__half2*)&u0.y);
                acc.x += w0 * f0a.x; acc.y += w0 * f0a.y;
                acc.z += w0 * f0b.x; acc.w += w0 * f0b.y;
            }
        }
        float inv = (end > beg) ? 1.f / den : 0.f;
        if (act) {
            float4 b = *(const float4*)(bias + lane * 4);
            acc.x = fmaf(acc.x, inv, b.x);
            acc.y = fmaf(acc.y, inv, b.y);
            acc.z = fmaf(acc.z, inv, b.z);
            acc.w = fmaf(acc.w, inv, b.w);
            *(float4*)(out + (size_t)gw * C + lane * 4) = acc;
            int c = lane * 4;
            atomicAdd(&s_sum[c + 0], acc.x); atomicAdd(&s_sq[c + 0], acc.x * acc.x);
            atomicAdd(&s_sum[c + 1], acc.y); atomicAdd(&s_sq[c + 1], acc.y * acc.y);
            atomicAdd(&s_sum[c + 2], acc.z); atomicAdd(&s_sq[c + 2], acc.z * acc.z);
            atomicAdd(&s_sum[c + 3], acc.w); atomicAdd(&s_sq[c + 3], acc.w * acc.w);
        }
    }
    __syncthreads();
    for (int c = tid; c < C; c += 256) {
        atomicAdd(&g_bnacc[accoff + c], s_sum[c]);
        atomicAdd(&g_bnacc[accoff + 128 + c], s_sq[c]);
    }
    // last-block BN finalize
    __threadfence();
    __syncthreads();
    if (tid == 0) s_ticket = atomicAdd(&g_ctr[cidx], 1u);
    __syncthreads();
    if (s_ticket == gridDim.x - 1) {
        __threadfence();
        if (tid < C) {
            float sum = __ldcg(&g_bnacc[accoff + tid]);
            float sq  = __ldcg(&g_bnacc[accoff + 128 + tid]);
            float mean = sum * (1.f / NN);
            float var = sq * (1.f / NN) - mean * mean;
            float sc = bgam[tid] * rsqrtf(var + 1e-5f);
            g_scale[scoff + tid] = sc;
            g_shift[scoff + tid] = bbet[tid] - mean * sc;
            g_bnacc[accoff + tid] = 0.f;
            g_bnacc[accoff + 128 + tid] = 0.f;
        }
        if (tid == 0) g_ctr[cidx] = 0u;
    }
}

// ---------------- final BN apply ---------------------------------------------
__global__ void k_out(const float* __restrict__ h, float* __restrict__ out) {
    int idx = blockIdx.x * blockDim.x + threadIdx.x;
    int i4 = idx * 4;
    if (i4 < NN * 112) {
        int c = i4 % 112;
        float4 v = *(const float4*)(h + i4);
        v.x = fmaf(v.x, g_scale[128 + c + 0], g_shift[128 + c + 0]);
        v.y = fmaf(v.y, g_scale[128 + c + 1], g_shift[128 + c + 1]);
        v.z = fmaf(v.z, g_scale[128 + c + 2], g_shift[128 + c + 2]);
        v.w = fmaf(v.w, g_scale[128 + c + 3], g_shift[128 + c + 3]);
        *(float4*)(out + i4) = v;
    }
}

// ---------------- launch -----------------------------------------------------
extern "C" void kernel_launch(void* const* d_in, const int* in_sizes, int n_in,
                              void* d_out, int out_size) {
    const float* x    = (const float*)d_in[0];
    const int*   ei   = (const int*)d_in[1];
    const float* eatt = (const float*)d_in[2];
    const float* W0   = (const float*)d_in[3];
    const float* as0  = (const float*)d_in[4];
    const float* ad0  = (const float*)d_in[5];
    const float* We0  = (const float*)d_in[6];
    const float* ae0  = (const float*)d_in[7];
    const float* b0   = (const float*)d_in[8];
    const float* W1   = (const float*)d_in[9];
    const float* as1  = (const float*)d_in[10];
    const float* ad1  = (const float*)d_in[11];
    const float* We1  = (const float*)d_in[12];
    const float* ae1  = (const float*)d_in[13];
    const float* b1   = (const float*)d_in[14];
    const float* bng  = (const float*)d_in[15];
    const float* bnb  = (const float*)d_in[16];
    const float* bfg  = (const float*)d_in[17];
    const float* bfb  = (const float*)d_in[18];
    float* out = (float*)d_out;

    const int* src = ei;
    const int* dst = ei + EE;

    __half2* p_xsh = nullptr;
    float* p_h = nullptr;
    cudaGetSymbolAddress((void**)&p_xsh, g_xsh);
    cudaGetSymbolAddress((void**)&p_h, g_h);

    static cudaStream_t s1 = nullptr, s2 = nullptr;
    static cudaEvent_t evFork = nullptr, evJoin = nullptr, ev2 = nullptr;
    if (!s1) {
        cudaStreamCreateWithFlags(&s1, cudaStreamNonBlocking);
        cudaStreamCreateWithFlags(&s2, cudaStreamNonBlocking);
        cudaEventCreateWithFlags(&evFork, cudaEventDisableTiming);
        cudaEventCreateWithFlags(&evJoin, cudaEventDisableTiming);
        cudaEventCreateWithFlags(&ev2, cudaEventDisableTiming);
    }

    const int TB = 256;
    const int gE = (EE + TB - 1) / TB;
    const int gE4 = (EE / 4 + TB - 1) / TB;
    const int gW8 = (NN + 63) / 64;
    const int gG = (NN + 127) / 128;

    // ---- fork: s1 = hist/scan, s2 = ced+aeF; join at scatter; gemm0 on main
    cudaEventRecord(evFork, 0);
    cudaStreamWaitEvent(s1, evFork, 0);
    cudaStreamWaitEvent(s2, evFork, 0);

    k_hist<<<gE4, TB, 0, s1>>>((const int4*)dst);
    k_scan_part<<<NBLK, 1024, 0, s1>>>();
    k_scan_apply<<<NBLK, 1024, 0, s1>>>();
    k_gemm<128, false><<<gG, 256>>>(x, W0, as0, ad0, p_xsh);    // profiled slot
    k_ced<<<1, 32, 0, s2>>>(We0, ae0, We1, ae1);
    k_aeF<<<gE, TB, 0, s2>>>(eatt);
    cudaEventRecord(ev2, s2);
    cudaStreamWaitEvent(s1, ev2, 0);
    k_scatter<<<gE, TB, 0, s1>>>(src, dst);
    cudaEventRecord(evJoin, s1);

    cudaStreamWaitEvent(0, evJoin, 0);

    // ---- layer 0 (alpha inline, BN finalize fused)
    k_agg<128, 0><<<gW8, TB>>>(b0, p_h, bng, bnb, 0, 0, 0);

    // ---- layer 1 (BN+relu fused into A-load; alpha inline; BN fused)
    k_gemm<112, true><<<gG, 256>>>(p_h, W1, as1, ad1, p_xsh);
    k_agg<112, 1><<<gW8, TB>>>(b1, p_h, bfg, bfb, 256, 128, 1);
    k_out<<<(NN * 112 / 4 + TB - 1) / TB, TB>>>(p_h, out);
}